// round 13
// baseline (speedup 1.0000x reference)
#include <cuda_runtime.h>
#include <cuda_fp16.h>
#include <cstdint>

// SimpleGAT reduces exactly to out = inputs @ W (softmax over a broadcast-
// constant axis is uniform; the einsum multiplies H by sum_k(alpha)==1).
// fp32 GEMM M=131072, N=256, K=256 via mma.sync fp16 (base sm_103 target).
// Pure fp16 single-term scheme (calibrated rel_err 2.94e-4 vs 1e-3 gate).
// R12: per-warp A pipelines. W slice resident once (64KB, one barrier);
//      each warp cp.asyncs its OWN 16 A-rows (3 stages, depth-2) and syncs
//      with wait_group + __syncwarp only -> ZERO CTA barriers in mainloop.
//      Fixes R11 (direct-LDG latency) while keeping its barrier freedom;
//      fixes R9's barrier lockstep while keeping its coalesced cp.async path.

namespace cfg {
constexpr int KDIM = 256, NDIM = 256;
constexpr int BM = 256, BN = 128, KC = 32;
constexpr int NT = 512;                           // 16 warps, 16 rows x 128 cols each
constexpr int NCHUNK = KDIM / KC;                 // 8
constexpr int A_ROW_B = 160;                      // 40 floats/row: 2-phase min LDS.64
constexpr uint32_t A_STAGE = 16u * A_ROW_B;       // 2560 B per warp-stage
constexpr uint32_t A_WARP = 3 * A_STAGE;          // 3 stages per warp
constexpr uint32_t OFF_A = 0;                     // 16 warps x 7680 = 122880
constexpr uint32_t OFF_W = 16 * A_WARP;           // 122880
constexpr int W_STRIDE_B = 528;                   // 256 fp16 + 16B pad: conflict-free LDSM
constexpr uint32_t SMEM_TOTAL = OFF_W + 128u * W_STRIDE_B;  // 190464 -> 1 CTA/SM
}  // namespace cfg

// W transposed to fp16 [n][k].
__device__ __half g_Wh[cfg::NDIM * cfg::KDIM];

// ---------------- helpers ----------------
__device__ __forceinline__ uint32_t smem_u32(const void* p) {
    uint32_t a;
    asm("{ .reg .u64 t; cvta.to.shared.u64 t, %1; cvt.u32.u64 %0, t; }" : "=r"(a) : "l"(p));
    return a;
}
__device__ __forceinline__ void cp_async16(uint32_t dst, const void* src) {
    asm volatile("cp.async.cg.shared.global [%0], [%1], 16;" :: "r"(dst), "l"(src));
}
__device__ __forceinline__ void cp_commit() { asm volatile("cp.async.commit_group;"); }
template <int N>
__device__ __forceinline__ void cp_wait() {
    asm volatile("cp.async.wait_group %0;" :: "n"(N) : "memory");
}
__device__ __forceinline__ void ldsm_x4(uint32_t* r, uint32_t addr) {
    asm volatile("ldmatrix.sync.aligned.m8n8.x4.shared.b16 {%0,%1,%2,%3}, [%4];"
                 : "=r"(r[0]), "=r"(r[1]), "=r"(r[2]), "=r"(r[3]) : "r"(addr));
}
__device__ __forceinline__ float2 lds64(uint32_t addr) {
    float2 v;
    asm volatile("ld.shared.v2.f32 {%0,%1}, [%2];" : "=f"(v.x), "=f"(v.y) : "r"(addr));
    return v;
}
__device__ __forceinline__ void mma_f16(float* c, const uint32_t* a, const uint32_t* b) {
    asm volatile(
        "mma.sync.aligned.m16n8k16.row.col.f32.f16.f16.f32 "
        "{%0,%1,%2,%3}, {%4,%5,%6,%7}, {%8,%9}, {%0,%1,%2,%3};"
        : "+f"(c[0]), "+f"(c[1]), "+f"(c[2]), "+f"(c[3])
        : "r"(a[0]), "r"(a[1]), "r"(a[2]), "r"(a[3]), "r"(b[0]), "r"(b[1]));
}
__device__ __forceinline__ uint32_t cvt_f16x2(float2 v) {
    uint32_t r;
    asm("cvt.rn.f16x2.f32 %0, %1, %2;" : "=r"(r) : "f"(v.y), "f"(v.x));
    return r;
}

// ---------------- kernels ----------------

__global__ void gat_prep_w(const float* __restrict__ W) {
    using namespace cfg;
    int idx = blockIdx.x * blockDim.x + threadIdx.x;  // 65536
    int k = idx >> 8, n = idx & 255;
    g_Wh[n * KDIM + k] = __float2half_rn(W[idx]);
}

__global__ __launch_bounds__(cfg::NT, 1)
void gat_mma_gemm(const float* __restrict__ A, float* __restrict__ C) {
    using namespace cfg;
    extern __shared__ char smem[];
    const uint32_t sb = smem_u32(smem);

    const int tid = threadIdx.x;
    const int wid = tid >> 5, lane = tid & 31;   // warp: rows wid*16..+15, cols 0..127
    const size_t rowBase = (size_t)blockIdx.y * BM;
    const int colBase = blockIdx.x * BN;

    // ---- group 1: one-shot W slice (128 rows x 512B), 8 x 16B per thread ----
    {
        const int r = tid >> 2;
        const int s0 = (tid & 3) * 8;
        const uint32_t dbase = sb + OFF_W + (uint32_t)r * W_STRIDE_B;
        const __half* src = g_Wh + (size_t)(colBase + r) * KDIM;
#pragma unroll
        for (int i = 0; i < 8; i++)
            cp_async16(dbase + (s0 + i) * 16, src + (s0 + i) * 8);
        cp_commit();
    }

    // ---- per-warp A chunk loader: 16 rows x 128B, 4 x 16B per lane ----
    const uint32_t aWarpBase = sb + OFF_A + (uint32_t)wid * A_WARP;
    const int aLdRow = lane >> 1;              // 16 rows, 2 lanes each
    const int aLdSeg = (lane & 1) * 4;         // 4 of 8 segs per lane
    const float* aSrcBase = A + (rowBase + wid * 16 + aLdRow) * KDIM + aLdSeg * 4;

    auto cp_A = [&](int c) {                   // one commit group per lane
        const uint32_t dst = aWarpBase + (uint32_t)(c % 3) * A_STAGE
                           + (uint32_t)aLdRow * A_ROW_B + aLdSeg * 16;
        const float* src = aSrcBase + c * KC;
#pragma unroll
        for (int i = 0; i < 4; i++)
            cp_async16(dst + i * 16, src + i * 4);
        cp_commit();
    };

    // prologue: groups [W][A0][A1]; force W+A0, let A1 fly
    cp_A(0);
    cp_A(1);
    cp_wait<1>();
    __syncthreads();     // W visible CTA-wide; the ONLY CTA barrier before epilogue

    // per-lane fragment address components
    const int g = lane >> 2;
    const uint32_t aOff = (uint32_t)g * A_ROW_B + (uint32_t)(lane & 3) * 8;
    const uint32_t wOff = (uint32_t)(lane & 15) * W_STRIDE_B + (uint32_t)((lane >> 4) << 4);

    float acc[16][4];
#pragma unroll
    for (int n = 0; n < 16; n++)
#pragma unroll
        for (int q = 0; q < 4; q++) acc[n][q] = 0.0f;

#pragma unroll 1
    for (int c = 0; c < NCHUNK; c++) {
        // depth-2 prefetch into stage (c+2)%3 — last read by THIS warp at c-1
        if (c + 2 < NCHUNK) {
            cp_A(c + 2);
            cp_wait<2>();          // forces A(c); A(c+1), A(c+2) in flight
        } else if (c + 1 < NCHUNK) {
            cp_wait<1>();          // c == 6: forces A(6)
        } else {
            cp_wait<0>();          // c == 7: forces A(7)
        }
        __syncwarp();              // warp-local visibility of A stage

        const uint32_t aBase = aWarpBase + (uint32_t)(c % 3) * A_STAGE + aOff;

#pragma unroll
        for (int s = 0; s < 2; s++) {
            // --- A fragment (16x16): 4 x LDS.64 + 4 x cvt ---
            uint32_t aF[4];
            {
                const uint32_t b0 = aBase + (uint32_t)s * 64;
                aF[0] = cvt_f16x2(lds64(b0));
                aF[1] = cvt_f16x2(lds64(b0 + 8 * A_ROW_B));
                aF[2] = cvt_f16x2(lds64(b0 + 32));
                aF[3] = cvt_f16x2(lds64(b0 + 8 * A_ROW_B + 32));
            }
            const uint32_t kOff = (uint32_t)(c * 64 + s * 32);  // bytes into W row
            // 16 n-tiles in two halves (caps live B regs at 16)
#pragma unroll
            for (int h = 0; h < 2; h++) {
                uint32_t bF[8][2];
#pragma unroll
                for (int p = 0; p < 4; p++) {
                    uint32_t r[4];
                    ldsm_x4(r, sb + OFF_W + wOff
                              + (uint32_t)(h * 64 + p * 16) * W_STRIDE_B + kOff);
                    bF[2 * p][0] = r[0]; bF[2 * p][1] = r[2];
                    bF[2 * p + 1][0] = r[1]; bF[2 * p + 1][1] = r[3];
                }
#pragma unroll
                for (int n = 0; n < 8; n++) mma_f16(acc[h * 8 + n], aF, bF[n]);
            }
        }
    }

    // ---- epilogue: warp wid -> rows wid*16..+15, cols 0..127 ----
    const int tg = lane & 3;
    const size_t m0 = rowBase + wid * 16 + g;
#pragma unroll
    for (int n = 0; n < 16; n++) {
        const int col = colBase + n * 8 + tg * 2;
        *reinterpret_cast<float2*>(C + m0 * NDIM + col) =
            make_float2(acc[n][0], acc[n][1]);
        *reinterpret_cast<float2*>(C + (m0 + 8) * NDIM + col) =
            make_float2(acc[n][2], acc[n][3]);
    }
}

extern "C" void kernel_launch(void* const* d_in, const int* in_sizes, int n_in,
                              void* d_out, int out_size) {
    using namespace cfg;
    const float* A = (const float*)d_in[0];   // inputs [B,T,K] -> [M, 256]
    const float* W = (const float*)d_in[1];   // W [256, 256]
    float* C = (float*)d_out;

    const int M = in_sizes[0] / KDIM;         // 131072

    cudaFuncSetAttribute(gat_mma_gemm, cudaFuncAttributeMaxDynamicSharedMemorySize, SMEM_TOTAL);

    gat_prep_w<<<(KDIM * NDIM) / 256, 256>>>(W);
    dim3 grid(NDIM / BN, M / BM);
    gat_mma_gemm<<<grid, NT, SMEM_TOTAL>>>(A, C);
}

// round 14
// speedup vs baseline: 1.2701x; 1.2701x over previous
#include <cuda_runtime.h>
#include <cuda_fp16.h>
#include <cstdint>

// SimpleGAT reduces exactly to out = inputs @ W (softmax over a broadcast-
// constant axis is uniform; the einsum multiplies H by sum_k(alpha)==1).
// fp32 GEMM M=131072, N=256, K=256 via mma.sync fp16 (base sm_103 target).
// Pure fp16 single-term scheme (calibrated rel_err 2.94e-4 vs 1e-3 gate).
// R13: R9 config (best: 90.6us) + fragment-level software pipelining.
//      Each chunk has 4 fragment groups (2 k-steps x 2 n-halves); group g+1's
//      LDS/cvt/LDSM issue BEFORE group g's MMAs so shared-mem latency hides
//      under the tensor stream. (R11/R12 structural rewrites both regressed;
//      this keeps R9's memory architecture untouched.)

namespace cfg {
constexpr int KDIM = 256, NDIM = 256;
constexpr int BM = 128, BN = 128, KC = 32;
constexpr int NT = 256;                         // 8 warps
constexpr int NCHUNK = KDIM / KC;               // 8
constexpr int A_STRIDE_B = 160;                 // 40 floats: conflict-free LDS.64
constexpr uint32_t A_STAGE = 128u * A_STRIDE_B; // 20480 B, 3 stages
constexpr int W_STRIDE_B = 80;                  // 32 fp16 + 16B pad: conflict-free LDSM
constexpr uint32_t W_STAGE = 128u * W_STRIDE_B; // 10240 B, 3 stages
constexpr uint32_t OFF_A = 0;
constexpr uint32_t OFF_W = 3 * A_STAGE;         // 61440
constexpr uint32_t SMEM_TOTAL = OFF_W + 3 * W_STAGE;  // 92160 -> 2 CTAs/SM
}  // namespace cfg

// W transposed to fp16 [n][k].
__device__ __half g_Wh[cfg::NDIM * cfg::KDIM];

// ---------------- helpers ----------------
__device__ __forceinline__ uint32_t smem_u32(const void* p) {
    uint32_t a;
    asm("{ .reg .u64 t; cvta.to.shared.u64 t, %1; cvt.u32.u64 %0, t; }" : "=r"(a) : "l"(p));
    return a;
}
__device__ __forceinline__ void cp_async16(uint32_t dst, const void* src) {
    asm volatile("cp.async.cg.shared.global [%0], [%1], 16;" :: "r"(dst), "l"(src));
}
__device__ __forceinline__ void cp_commit() { asm volatile("cp.async.commit_group;"); }
template <int N>
__device__ __forceinline__ void cp_wait() {
    asm volatile("cp.async.wait_group %0;" :: "n"(N) : "memory");
}
__device__ __forceinline__ void ldsm_x4(uint32_t* r, uint32_t addr) {
    asm volatile("ldmatrix.sync.aligned.m8n8.x4.shared.b16 {%0,%1,%2,%3}, [%4];"
                 : "=r"(r[0]), "=r"(r[1]), "=r"(r[2]), "=r"(r[3]) : "r"(addr));
}
__device__ __forceinline__ float2 lds64(uint32_t addr) {
    float2 v;
    asm volatile("ld.shared.v2.f32 {%0,%1}, [%2];" : "=f"(v.x), "=f"(v.y) : "r"(addr));
    return v;
}
__device__ __forceinline__ void mma_f16(float* c, const uint32_t* a, const uint32_t* b) {
    asm volatile(
        "mma.sync.aligned.m16n8k16.row.col.f32.f16.f16.f32 "
        "{%0,%1,%2,%3}, {%4,%5,%6,%7}, {%8,%9}, {%0,%1,%2,%3};"
        : "+f"(c[0]), "+f"(c[1]), "+f"(c[2]), "+f"(c[3])
        : "r"(a[0]), "r"(a[1]), "r"(a[2]), "r"(a[3]), "r"(b[0]), "r"(b[1]));
}
// pack two fp32 -> one fp16x2 (lo = x, hi = y), round-to-nearest
__device__ __forceinline__ uint32_t cvt_f16x2(float2 v) {
    uint32_t r;
    asm("cvt.rn.f16x2.f32 %0, %1, %2;" : "=r"(r) : "f"(v.y), "f"(v.x));
    return r;
}

// ---------------- kernels ----------------

__global__ void gat_prep_w(const float* __restrict__ W) {
    using namespace cfg;
    int idx = blockIdx.x * blockDim.x + threadIdx.x;  // 65536
    int k = idx >> 8, n = idx & 255;
    g_Wh[n * KDIM + k] = __float2half_rn(W[idx]);
}

__global__ __launch_bounds__(cfg::NT, 2)
void gat_mma_gemm(const float* __restrict__ A, float* __restrict__ C) {
    using namespace cfg;
    extern __shared__ char smem[];
    const uint32_t sb = smem_u32(smem);

    const int tid = threadIdx.x;
    const int wid = tid >> 5, lane = tid & 31;   // warp owns rows wid*16..+15, all 128 cols
    const size_t rowBase = (size_t)blockIdx.y * BM;
    const int colBase = blockIdx.x * BN;

    // A cp.async: 1024 16B segs per stage, 4 per thread
    const int cpRow = tid >> 3;        // +32*i
    const int cpSeg = tid & 7;
    // W cp.async: 512 16B segs per stage, 2 per thread
    const int wRowLd = tid >> 1;               // 0..127
    const int wSegLd = (tid & 1) * 2;          // segs {0,1} or {2,3}

    auto cp_A = [&](int c) {           // one commit group
        const uint32_t base = sb + OFF_A + (uint32_t)(c % 3) * A_STAGE;
        const float* src = A + (rowBase + cpRow) * KDIM + c * KC + cpSeg * 4;
#pragma unroll
        for (int i = 0; i < 4; i++)
            cp_async16(base + (uint32_t)(cpRow + i * 32) * A_STRIDE_B + cpSeg * 16,
                       src + (size_t)i * 32 * KDIM);
        cp_commit();
    };
    auto cp_W = [&](int c) {           // one commit group
        const uint32_t base = sb + OFF_W + (uint32_t)(c % 3) * W_STAGE
                            + (uint32_t)wRowLd * W_STRIDE_B;
        const __half* src = g_Wh + (size_t)(colBase + wRowLd) * KDIM + c * KC;
#pragma unroll
        for (int i = 0; i < 2; i++)
            cp_async16(base + (wSegLd + i) * 16, src + (wSegLd + i) * 8);
        cp_commit();
    };

    // prologue: groups A0,W0,A1,W1; force A0,W0; A1,W1 may still fly
    cp_A(0); cp_W(0);
    cp_A(1); cp_W(1);
    cp_wait<2>();
    __syncthreads();

    // per-lane fragment address components
    const uint32_t aOff = (uint32_t)(wid * 16 + (lane >> 2)) * A_STRIDE_B + (lane & 3) * 8;
    const uint32_t wRow = (uint32_t)(lane & 15);
    const uint32_t wKo = (uint32_t)((lane >> 4) << 3);  // elems

    float acc[16][4];
#pragma unroll
    for (int n = 0; n < 16; n++)
#pragma unroll
        for (int q = 0; q < 4; q++) acc[n][q] = 0.0f;

    // fragment loaders (register destinations passed in)
    auto loadA = [&](uint32_t aBase, int s, uint32_t* f) {
        const uint32_t b0 = aBase + (uint32_t)s * 64;
        f[0] = cvt_f16x2(lds64(b0));
        f[1] = cvt_f16x2(lds64(b0 + 8 * A_STRIDE_B));
        f[2] = cvt_f16x2(lds64(b0 + 32));
        f[3] = cvt_f16x2(lds64(b0 + 8 * A_STRIDE_B + 32));
    };
    auto loadB = [&](uint32_t wBase, int s, int h, uint32_t (*bF)[2]) {
        const uint32_t kcol = (uint32_t)(s * 16) + wKo;
        const uint32_t rowOff = (wRow + (uint32_t)h * 64) * W_STRIDE_B;
#pragma unroll
        for (int p = 0; p < 4; p++) {
            uint32_t r[4];
            ldsm_x4(r, wBase + rowOff + p * 16 * W_STRIDE_B + kcol * 2);
            bF[2 * p][0] = r[0]; bF[2 * p][1] = r[2];
            bF[2 * p + 1][0] = r[1]; bF[2 * p + 1][1] = r[3];
        }
    };

#pragma unroll 1
    for (int c = 0; c < NCHUNK; c++) {
        // depth-2 prefetch; stage (c+2)%3 was last read by compute(c-1),
        // which finished before the barrier ending iter c-1.
        if (c + 2 < NCHUNK) { cp_A(c + 2); cp_W(c + 2); }

        const uint32_t aBase = sb + OFF_A + (uint32_t)(c % 3) * A_STAGE + aOff;
        const uint32_t wBase = sb + OFF_W + (uint32_t)(c % 3) * W_STAGE;

        // ---- 4 fragment groups, software-pipelined: load(g+1) before MMA(g) ----
        uint32_t aF[2][4];
        uint32_t bF[2][8][2];

        loadA(aBase, 0, aF[0]);
        loadB(wBase, 0, 0, bF[0]);

        // group (s0,h0): prefetch (s0,h1), then MMA
        loadB(wBase, 0, 1, bF[1]);
#pragma unroll
        for (int n = 0; n < 8; n++) mma_f16(acc[n], aF[0], bF[0][n]);

        // group (s0,h1): prefetch aF(s1) + (s1,h0), then MMA
        loadA(aBase, 1, aF[1]);
        loadB(wBase, 1, 0, bF[0]);
#pragma unroll
        for (int n = 0; n < 8; n++) mma_f16(acc[8 + n], aF[0], bF[1][n]);

        // group (s1,h0): prefetch (s1,h1), then MMA
        loadB(wBase, 1, 1, bF[1]);
#pragma unroll
        for (int n = 0; n < 8; n++) mma_f16(acc[n], aF[1], bF[0][n]);

        // group (s1,h1): drain (chunk boundary — next stage not yet waited)
#pragma unroll
        for (int n = 0; n < 8; n++) mma_f16(acc[8 + n], aF[1], bF[1][n]);

        if (c + 1 < NCHUNK) {
            // ensure groups for chunk c+1 landed; allow the 2 newest to fly
            if (c + 2 < NCHUNK) cp_wait<2>();
            else cp_wait<0>();
            __syncthreads();
        }
    }

    // ---- epilogue: warp wid -> rows wid*16..+15, cols 0..127 ----
    const int g = lane >> 2, tg = lane & 3;
    const size_t m0 = rowBase + wid * 16 + g;
#pragma unroll
    for (int n = 0; n < 16; n++) {
        const int col = colBase + n * 8 + tg * 2;
        *reinterpret_cast<float2*>(C + m0 * NDIM + col) =
            make_float2(acc[n][0], acc[n][1]);
        *reinterpret_cast<float2*>(C + (m0 + 8) * NDIM + col) =
            make_float2(acc[n][2], acc[n][3]);
    }
}

extern "C" void kernel_launch(void* const* d_in, const int* in_sizes, int n_in,
                              void* d_out, int out_size) {
    using namespace cfg;
    const float* A = (const float*)d_in[0];   // inputs [B,T,K] -> [M, 256]
    const float* W = (const float*)d_in[1];   // W [256, 256]
    float* C = (float*)d_out;

    const int M = in_sizes[0] / KDIM;         // 131072

    cudaFuncSetAttribute(gat_mma_gemm, cudaFuncAttributeMaxDynamicSharedMemorySize, SMEM_TOTAL);

    gat_prep_w<<<(KDIM * NDIM) / 256, 256>>>(W);
    dim3 grid(NDIM / BN, M / BM);
    gat_mma_gemm<<<grid, NT, SMEM_TOTAL>>>(A, C);
}